// round 5
// baseline (speedup 1.0000x reference)
#include <cuda_runtime.h>
#include <cstdint>
#include <cfloat>

// Problem constants
#define F 4096      // nb_features
#define C 64        // coord dim
#define B 1024      // batch
#define K 16        // nb_neighbors
#define J (F*K + 1) // 65537 gathered columns

// Scratch (no allocations allowed)
__device__ float g_sq[F];
__device__ int   g_cols[J];
__device__ float g_pd[2 * F * K];   // partial top-k distances (2 g-halves)
__device__ int   g_pi[2 * F * K];   // partial top-k indices

__device__ __forceinline__ bool lexlt(float d, int g, float v, int i) {
    return (d < v) || (d == v && g < i);
}

// ---------------------------------------------------------------------------
// Kernel 1: per-feature squared norms (UNFUSED mul+add, sequential — matches
// the reference's square+reduce rounding; rel_err is exactly 0 with this).
// ---------------------------------------------------------------------------
__global__ __launch_bounds__(256) void k_sq(const float* __restrict__ coord) {
    int f = blockIdx.x * 256 + threadIdx.x;
    float s = 0.f;
#pragma unroll
    for (int c = 0; c < C; ++c) {
        float x = coord[c * F + f];
        s = __fadd_rn(s, __fmul_rn(x, x));
    }
    g_sq[f] = s;
}

// ---------------------------------------------------------------------------
// Kernel 2: register-blocked distance GEMM + fused top-16.
//   Register-pressure-safe: 8x4 micro-tile (32 accs), unroll 2, 2 CTAs/SM.
//   Grid: 64 row-tiles x 2 g-halves = 128 CTAs, 256 threads.
//   CTA tile: 64 rows x 2048 g, inner g tiles of 128.
// ---------------------------------------------------------------------------
#define ROWS_CTA 64
#define GHALF    2048
#define TGG      128
#define NTL      (GHALF / TGG)   // 16
#define DPITCH   132             // s_d row pitch (floats): 132 % 32 = 4

// smem layout (floats)
#define OFF_F    0                          // 64c x 64r = 4096
#define OFF_SQF  (OFF_F + C * ROWS_CTA)     // 64
#define OFF_G    (OFF_SQF + ROWS_CTA)       // 64c x 128g = 8192
#define OFF_SQG  (OFF_G + C * TGG)          // 128
#define OFF_D    (OFF_SQG + TGG)            // 64 x 132 = 8448
#define SMEM_D_FLOATS (OFF_D + ROWS_CTA * DPITCH)
#define SMEM_D_BYTES  (SMEM_D_FLOATS * 4)   // 83712 B -> 2 CTAs/SM

__global__ __launch_bounds__(256, 2) void k_dist(const float* __restrict__ coord) {
    extern __shared__ float sm[];
    float* s_f   = sm + OFF_F;
    float* s_sqf = sm + OFF_SQF;
    float* s_g   = sm + OFF_G;
    float* s_sqg = sm + OFF_SQG;
    float* s_d   = sm + OFF_D;

    const int tid  = threadIdx.x;
    const int tx   = tid & 31;    // g float4 group (warp lane)
    const int ty   = tid >> 5;    // row group = warp id (warp-uniform)
    const int f0   = (blockIdx.x >> 1) * ROWS_CTA;
    const int half = blockIdx.x & 1;
    const int g0   = half * GHALF;

    // stage f tile: s_f[c*64 + r] = coord[c][f0+r]
    for (int idx = tid; idx < (C * ROWS_CTA) / 4; idx += 256) {
        int c = idx >> 4, r4 = (idx & 15) * 4;
        *(float4*)(s_f + c * ROWS_CTA + r4) = *(const float4*)(coord + c * F + f0 + r4);
    }
    if (tid < ROWS_CTA / 4)
        *(float4*)(s_sqf + tid * 4) = *(const float4*)(g_sq + f0 + tid * 4);

    // top-k scan state: thread = (srow, sq), scans g = sq + 4*i (bank-clean)
    const int srow = tid >> 2, sq = tid & 3;
    float vv[K]; int ii[K];
#pragma unroll
    for (int j = 0; j < K; ++j) { vv[j] = FLT_MAX; ii[j] = 0x7FFFFFFF; }
    float thr2 = FLT_MAX;   // conservative squared threshold (no false negatives)

    for (int t = 0; t < NTL; ++t) {
        const int gb = g0 + t * TGG;
        __syncthreads();   // prev scan done; safe to overwrite s_g/s_d
        for (int idx = tid; idx < (C * TGG) / 4; idx += 256) {
            int c = idx >> 5, o4 = (idx & 31) * 4;
            *(float4*)(s_g + c * TGG + o4) = *(const float4*)(coord + c * F + gb + o4);
        }
        if (tid < TGG / 4)
            *(float4*)(s_sqg + tid * 4) = *(const float4*)(g_sq + gb + tid * 4);
        __syncthreads();

        // ---- compute 8x4 micro-tile: rows ty*8..+7, g = tx*4+{0..3} ----
        float acc[8][4];
#pragma unroll
        for (int r = 0; r < 8; ++r)
#pragma unroll
            for (int e = 0; e < 4; ++e) acc[r][e] = 0.f;

        const float* fp = s_f + ty * 8;
        const float* gp = s_g + tx * 4;
#pragma unroll 2
        for (int c = 0; c < C; ++c) {
            float4 a0 = *(const float4*)(fp + c * ROWS_CTA);      // broadcast
            float4 a1 = *(const float4*)(fp + c * ROWS_CTA + 4);  // broadcast
            float4 b  = *(const float4*)(gp + c * TGG);           // contiguous
            float av[8] = {a0.x, a0.y, a0.z, a0.w, a1.x, a1.y, a1.z, a1.w};
#pragma unroll
            for (int r = 0; r < 8; ++r) {
                acc[r][0] = __fmaf_rn(av[r], b.x, acc[r][0]);
                acc[r][1] = __fmaf_rn(av[r], b.y, acc[r][1]);
                acc[r][2] = __fmaf_rn(av[r], b.z, acc[r][2]);
                acc[r][3] = __fmaf_rn(av[r], b.w, acc[r][3]);
            }
        }

        // ---- finalize d2 and stage to s_d ----
        float sg0 = s_sqg[tx * 4 + 0];
        float sg1 = s_sqg[tx * 4 + 1];
        float sg2 = s_sqg[tx * 4 + 2];
        float sg3 = s_sqg[tx * 4 + 3];
#pragma unroll
        for (int r = 0; r < 8; ++r) {
            float sf = s_sqf[ty * 8 + r];
            float4 d;
            d.x = __fadd_rn(__fmaf_rn(-2.f, acc[r][0], sg0), sf);
            d.y = __fadd_rn(__fmaf_rn(-2.f, acc[r][1], sg1), sf);
            d.z = __fadd_rn(__fmaf_rn(-2.f, acc[r][2], sg2), sf);
            d.w = __fadd_rn(__fmaf_rn(-2.f, acc[r][3], sg3), sf);
            *(float4*)(s_d + (ty * 8 + r) * DPITCH + tx * 4) = d;
        }
        __syncthreads();

        // ---- top-k scan (prefilter on d2; exact sqrt path on survivors) ----
        const float* dr = s_d + srow * DPITCH;
        for (int i = 0; i < TGG / 4; ++i) {
            int go = sq + 4 * i;
            float d2 = dr[go];
            if (d2 <= thr2) {
                float d = sqrtf(fmaxf(d2, 0.f));
                int g = gb + go;
                if (lexlt(d, g, vv[K - 1], ii[K - 1])) {
                    float cv = d; int ci = g;
#pragma unroll
                    for (int j = 0; j < K; ++j) {
                        bool sw = lexlt(cv, ci, vv[j], ii[j]);
                        float tv = vv[j]; int ti = ii[j];
                        if (sw) { vv[j] = cv; ii[j] = ci; cv = tv; ci = ti; }
                    }
                    float v15 = vv[K - 1];
                    thr2 = (v15 >= FLT_MAX) ? FLT_MAX
                         : __uint_as_float(__float_as_uint(__fmul_ru(v15, v15)) + 8);
                }
            }
        }
    }

    // ---- merge 4 per-row lists -> partial top-16 (alias s_d as buffers) ----
    __syncthreads();
    float* s_mv = s_d;                              // [64][66]
    int*   s_mi = (int*)(s_d + ROWS_CTA * 66);      // [64][66]
    {
        int mb = srow * 66 + sq * K;
#pragma unroll
        for (int j = 0; j < K; ++j) { s_mv[mb + j] = vv[j]; s_mi[mb + j] = ii[j]; }
    }
    __syncthreads();

    if (tid < ROWS_CTA) {
        int mb = tid * 66;
        int h[4] = {0, 0, 0, 0};
        int outb = half * F * K + (f0 + tid) * K;
        for (int k = 0; k < K; ++k) {
            float bv = FLT_MAX; int bi = 0x7FFFFFFF; int bs = 0; bool any = false;
#pragma unroll
            for (int s = 0; s < 4; ++s) {
                if (h[s] < K) {
                    float v = s_mv[mb + s * K + h[s]];
                    int   i = s_mi[mb + s * K + h[s]];
                    if (!any || lexlt(v, i, bv, bi)) { bv = v; bi = i; bs = s; any = true; }
                }
            }
            g_pd[outb + k] = bv;
            g_pi[outb + k] = bi;
            h[bs]++;
        }
    }
}

// ---------------------------------------------------------------------------
// Kernel 3: merge the two g-half partial lists per feature -> g_cols
// ---------------------------------------------------------------------------
__global__ __launch_bounds__(256) void k_merge() {
    int f = blockIdx.x * 256 + threadIdx.x;
    int b0 = f * K;
    int b1 = F * K + f * K;
    int p0 = 0, p1 = 0;
    for (int k = 0; k < K; ++k) {
        float v0 = (p0 < K) ? g_pd[b0 + p0] : FLT_MAX;
        int   i0 = (p0 < K) ? g_pi[b0 + p0] : 0x7FFFFFFF;
        float v1 = (p1 < K) ? g_pd[b1 + p1] : FLT_MAX;
        int   i1 = (p1 < K) ? g_pi[b1 + p1] : 0x7FFFFFFF;
        bool take0 = lexlt(v0, i0, v1, i1);
        g_cols[1 + f * K + k] = take0 ? i0 : i1;
        if (take0) p0++; else p1++;
    }
    if (f == 0) g_cols[0] = 0;
}

// ---------------------------------------------------------------------------
// Kernel 4: gather. CTA caches 2 input rows (32 KB SMEM); per-row alignment-
// adjusted float4 streaming stores (J is odd, so each row re-aligns).
// ---------------------------------------------------------------------------
#define RB 2
#define GATHER_SMEM (RB * F * 4)

__global__ __launch_bounds__(256) void k_gather(const float* __restrict__ inputs,
                                                float* __restrict__ out) {
    extern __shared__ float s_in[];   // RB * 4096
    const int b0 = blockIdx.x * RB;
    const int tid = threadIdx.x;

    for (int idx = tid; idx < (RB * F) / 4; idx += 256) {
        int r = idx >> 10, q = idx & 1023;
        *(float4*)(s_in + r * F + q * 4) =
            *(const float4*)(inputs + (size_t)(b0 + r) * F + q * 4);
    }
    __syncthreads();

#pragma unroll
    for (int r = 0; r < RB; ++r) {
        const int b = b0 + r;
        const size_t rowbase = (size_t)b * J;
        const float* row = s_in + r * F;
        const int align = (int)((4u - ((unsigned)rowbase & 3u)) & 3u);
        const int nv = (J - align) >> 2;

        // head (< 4 scalar elements)
        for (int j = tid; j < align; j += 256) {
            int c = __ldg(&g_cols[j]);
            __stcs(out + rowbase + j, row[c]);
        }
        // aligned float4 body
        for (int m = tid; m < nv; m += 256) {
            int j = align + 4 * m;
            int c0 = __ldg(&g_cols[j + 0]);
            int c1 = __ldg(&g_cols[j + 1]);
            int c2 = __ldg(&g_cols[j + 2]);
            int c3 = __ldg(&g_cols[j + 3]);
            float4 v;
            v.x = row[c0]; v.y = row[c1]; v.z = row[c2]; v.w = row[c3];
            __stcs((float4*)(out + rowbase + j), v);
        }
        // tail (< 4 scalar elements)
        for (int j = align + 4 * nv + tid; j < J; j += 256) {
            int c = __ldg(&g_cols[j]);
            __stcs(out + rowbase + j, row[c]);
        }
    }
}

// ---------------------------------------------------------------------------
extern "C" void kernel_launch(void* const* d_in, const int* in_sizes, int n_in,
                              void* d_out, int out_size) {
    const float* inputs = (const float*)d_in[0];
    const float* coord  = (const float*)d_in[1];
    if (n_in >= 2 && in_sizes[0] < in_sizes[1]) {
        const float* t = inputs; inputs = coord; coord = t;
    }
    float* out = (float*)d_out;

    static bool attr_done = false;
    if (!attr_done) {
        cudaFuncSetAttribute(k_dist, cudaFuncAttributeMaxDynamicSharedMemorySize,
                             SMEM_D_BYTES);
        cudaFuncSetAttribute(k_gather, cudaFuncAttributeMaxDynamicSharedMemorySize,
                             GATHER_SMEM);
        attr_done = true;
    }

    k_sq<<<F / 256, 256>>>(coord);
    k_dist<<<(F / ROWS_CTA) * 2, 256, SMEM_D_BYTES>>>(coord);
    k_merge<<<F / 256, 256>>>();
    k_gather<<<B / RB, 256, GATHER_SMEM>>>(inputs, out);
}